// round 1
// baseline (speedup 1.0000x reference)
#include <cuda_runtime.h>
#include <math.h>

#define B_   8
#define T_   512
#define FIN_ 256
#define D_   128
#define C_   16          // chunks per batch
#define L_   32          // chunk length (T_/C_)
#define SUB_ 16          // sub-tile of timesteps kept in smem

// ---------------- scratch (device globals; no runtime allocation) ----------------
__device__ __align__(16) float g_K[B_*T_*D_];
__device__ __align__(16) float g_Q[B_*T_*D_];
__device__ __align__(16) float g_V[B_*T_*D_];
__device__ __align__(16) float g_R[B_*T_*D_];      // xn @ Ws + bs
__device__ __align__(16) float g_num[B_*T_*D_];    // numerator
__device__ __align__(16) float g_Soff[B_*C_*D_*D_];// chunk sums -> exclusive prefix

// ---------------- k1: LayerNorm + 4 projections (K,Q,V,R) ----------------
// grid 128 blocks x 256 threads, 32 rows per block. dyn smem: xn[32][256] + W chunk[32][128]
__global__ void k1_ln_proj(const float* __restrict__ x,
                           const float* __restrict__ gamma, const float* __restrict__ beta,
                           const float* __restrict__ Wk, const float* __restrict__ Wq,
                           const float* __restrict__ Wv, const float* __restrict__ Ws,
                           const float* __restrict__ bs) {
    extern __shared__ float sm[];
    float* xb = sm;               // 32*256 floats
    float* wb = sm + 32*FIN_;     // 32*128 floats
    const int tid  = threadIdx.x;
    const int w    = tid >> 5, lane = tid & 31;
    const int row0 = blockIdx.x * 32;

    // load x tile
    const float4* xg = (const float4*)(x + (size_t)row0 * FIN_);
    for (int q = tid; q < 32*FIN_/4; q += 256) ((float4*)xb)[q] = xg[q];

    float gv[8], bv[8];
#pragma unroll
    for (int k = 0; k < 8; k++) { gv[k] = gamma[lane + 32*k]; bv[k] = beta[lane + 32*k]; }
    __syncthreads();

    // LayerNorm: warp per row (4 rows per warp), in-place normalize
#pragma unroll
    for (int rr = 0; rr < 4; rr++) {
        const int r = w*4 + rr;
        float s = 0.f, ss = 0.f, xv[8];
#pragma unroll
        for (int k = 0; k < 8; k++) { float v = xb[r*FIN_ + lane + 32*k]; xv[k] = v; s += v; ss += v*v; }
#pragma unroll
        for (int off = 16; off; off >>= 1) {
            s  += __shfl_xor_sync(0xffffffffu, s,  off);
            ss += __shfl_xor_sync(0xffffffffu, ss, off);
        }
        const float mu   = s * (1.0f/FIN_);
        const float rstd = rsqrtf(ss*(1.0f/FIN_) - mu*mu + 1e-5f);
#pragma unroll
        for (int k = 0; k < 8; k++)
            xb[r*FIN_ + lane + 32*k] = (xv[k]-mu)*rstd*gv[k] + bv[k];
    }
    __syncthreads();

    const float* Wm[4] = {Wk, Wq, Wv, Ws};
    float*       Om[4] = {g_K, g_Q, g_V, g_R};
    const int rowg = w, colg = lane;   // 8 x 32, micro-tile 4x4

    for (int m = 0; m < 4; m++) {
        float acc[4][4];
#pragma unroll
        for (int u = 0; u < 4; u++)
#pragma unroll
            for (int v = 0; v < 4; v++) acc[u][v] = 0.f;
        const float* Wp = Wm[m];
        for (int kc = 0; kc < FIN_; kc += 32) {
            __syncthreads();
            for (int q = tid; q < 32*D_/4; q += 256)
                ((float4*)wb)[q] = ((const float4*)(Wp + (size_t)kc*D_))[q];
            __syncthreads();
#pragma unroll
            for (int k = 0; k < 32; k++) {
                const float4 wv = ((const float4*)(wb + k*D_))[colg];
#pragma unroll
                for (int u = 0; u < 4; u++) {
                    const float a = xb[(rowg*4+u)*FIN_ + kc + k];
                    acc[u][0] += a*wv.x; acc[u][1] += a*wv.y;
                    acc[u][2] += a*wv.z; acc[u][3] += a*wv.w;
                }
            }
        }
        float badd[4] = {0.f,0.f,0.f,0.f};
        if (m == 3) { float4 t = ((const float4*)bs)[colg]; badd[0]=t.x; badd[1]=t.y; badd[2]=t.z; badd[3]=t.w; }
#pragma unroll
        for (int u = 0; u < 4; u++) {
            float o[4];
#pragma unroll
            for (int v = 0; v < 4; v++) {
                float val = acc[u][v];
                if (m <= 1) val = (val > 0.f) ? (val + 1.f) : expf(val);   // elu + 1
                o[v] = val + badd[v];
            }
            *(float4*)(Om[m] + ((size_t)(row0 + rowg*4 + u))*D_ + colg*4) =
                make_float4(o[0], o[1], o[2], o[3]);
        }
    }
}

// ---------------- k2: per-chunk outer-product sums  Ssum[b][c] = sum_t K[t] (x) V[t] ----------------
__global__ void k2_chunksum() {
    const int c = blockIdx.x, b = blockIdx.y;
    const int tid = threadIdx.x;   // 256
    __shared__ __align__(16) float Ks[L_][D_];
    __shared__ __align__(16) float Vs[L_][D_];
    {
        const float4* kg = (const float4*)(g_K + ((size_t)b*T_ + c*L_)*D_);
        const float4* vg = (const float4*)(g_V + ((size_t)b*T_ + c*L_)*D_);
        for (int q = tid; q < L_*D_/4; q += 256) { ((float4*)Ks)[q] = kg[q]; ((float4*)Vs)[q] = vg[q]; }
    }
    __syncthreads();
    const int tr = tid >> 4, tc = tid & 15;  // 16x16, micro 8x8
    const int i0 = tr*8, j0 = tc*8;
    float acc[8][8];
#pragma unroll
    for (int u = 0; u < 8; u++)
#pragma unroll
        for (int v = 0; v < 8; v++) acc[u][v] = 0.f;

    for (int t = 0; t < L_; t++) {
        float k8[8], v8[8];
        *(float4*)(k8)   = *(const float4*)&Ks[t][i0];
        *(float4*)(k8+4) = *(const float4*)&Ks[t][i0+4];
        *(float4*)(v8)   = *(const float4*)&Vs[t][j0];
        *(float4*)(v8+4) = *(const float4*)&Vs[t][j0+4];
#pragma unroll
        for (int u = 0; u < 8; u++)
#pragma unroll
            for (int v = 0; v < 8; v++) acc[u][v] += k8[u]*v8[v];
    }
    float* op = g_Soff + (((size_t)(b*C_ + c))*D_ + i0)*D_ + j0;
#pragma unroll
    for (int u = 0; u < 8; u++) {
        *(float4*)(op + (size_t)u*D_)     = make_float4(acc[u][0],acc[u][1],acc[u][2],acc[u][3]);
        *(float4*)(op + (size_t)u*D_ + 4) = make_float4(acc[u][4],acc[u][5],acc[u][6],acc[u][7]);
    }
}

// ---------------- k3: in-place exclusive scan of chunk sums over c ----------------
__global__ void k3_scan() {
    const int gid = blockIdx.x * blockDim.x + threadIdx.x;
    if (gid >= B_*D_*D_) return;
    const int b  = gid >> 14;            // D_*D_ = 16384
    const int ij = gid & (D_*D_ - 1);
    const size_t base = (size_t)b*C_*D_*D_ + ij;
    float run = 0.f;
#pragma unroll
    for (int c = 0; c < C_; c++) {
        const float tmp = g_Soff[base + (size_t)c*D_*D_];
        g_Soff[base + (size_t)c*D_*D_] = run;
        run += tmp;
    }
}

// ---------------- kZ: Z cumsum (thread per (b,i)) ----------------
__global__ void kZ_kernel(const float* __restrict__ Z0, float* __restrict__ outZ) {
    const int b = blockIdx.x;
    const int i = threadIdx.x;
    float z = Z0[b*D_ + i];
    const float* kp = g_K  + (size_t)b*T_*D_ + i;
    float*       zp = outZ + (size_t)b*T_*D_ + i;
#pragma unroll 8
    for (int t = 0; t < T_; t++) {
        z += *kp;
        *zp = z;
        kp += D_; zp += D_;
    }
}

// ---------------- k4: main scan — S state in registers, write S, compute numerator ----------------
__global__ void __launch_bounds__(1024, 1)
k4_main(const float* __restrict__ S0, float* __restrict__ outS) {
    const int c = blockIdx.x, b = blockIdx.y;
    const int tid = threadIdx.x;         // 1024
    const int ri = tid >> 5;             // 0..31  -> i block
    const int jg = tid & 31;             // 0..31  -> j block
    const int i0 = ri << 2, j0 = jg << 2;

    __shared__ __align__(16) float Ks[SUB_][D_];
    __shared__ __align__(16) float Vs[SUB_][D_];
    __shared__ __align__(16) float Qs[SUB_][D_];
    __shared__ __align__(16) float part[32][D_];

    float s[4][4];
    {
        const float* soff = g_Soff + (((size_t)(b*C_ + c))*D_ + i0)*D_ + j0;
        const float* s0g  = S0 + ((size_t)b*D_ + i0)*D_ + j0;
#pragma unroll
        for (int u = 0; u < 4; u++) {
            const float4 a = *(const float4*)(soff + (size_t)u*D_);
            const float4 z = *(const float4*)(s0g  + (size_t)u*D_);
            s[u][0] = a.x + z.x; s[u][1] = a.y + z.y;
            s[u][2] = a.z + z.z; s[u][3] = a.w + z.w;
        }
    }

    const int t0 = c * L_;
    for (int sub = 0; sub < L_/SUB_; sub++) {
        const int tg = t0 + sub*SUB_;
        {
            const float4* kg = (const float4*)(g_K + ((size_t)b*T_ + tg)*D_);
            const float4* vg = (const float4*)(g_V + ((size_t)b*T_ + tg)*D_);
            const float4* qg = (const float4*)(g_Q + ((size_t)b*T_ + tg)*D_);
            const int h = tid & 511;     // SUB_*D_/4 = 512
            if (tid < 512) { ((float4*)Ks)[h] = kg[h]; ((float4*)Vs)[h] = vg[h]; }
            else           { ((float4*)Qs)[h] = qg[h]; }
        }
        __syncthreads();

        for (int tt = 0; tt < SUB_; tt++) {
            const int t = tg + tt;
            const float4 kv = *(const float4*)&Ks[tt][i0];
            const float4 vv = *(const float4*)&Vs[tt][j0];
            const float4 qv = *(const float4*)&Qs[tt][i0];
            const float kk[4] = {kv.x, kv.y, kv.z, kv.w};
            const float vb[4] = {vv.x, vv.y, vv.z, vv.w};
            const float qq[4] = {qv.x, qv.y, qv.z, qv.w};
            float p0 = 0.f, p1 = 0.f, p2 = 0.f, p3 = 0.f;
            float* orow = outS + (((size_t)b*T_ + t)*D_ + i0)*D_ + j0;
#pragma unroll
            for (int u = 0; u < 4; u++) {
                s[u][0] += kk[u]*vb[0];
                s[u][1] += kk[u]*vb[1];
                s[u][2] += kk[u]*vb[2];
                s[u][3] += kk[u]*vb[3];
                *(float4*)(orow + (size_t)u*D_) = make_float4(s[u][0], s[u][1], s[u][2], s[u][3]);
                p0 += qq[u]*s[u][0];
                p1 += qq[u]*s[u][1];
                p2 += qq[u]*s[u][2];
                p3 += qq[u]*s[u][3];
            }
            *(float4*)&part[ri][j0] = make_float4(p0, p1, p2, p3);
            __syncthreads();
            if (tid < D_) {
                float sum = 0.f;
#pragma unroll
                for (int rr = 0; rr < 32; rr++) sum += part[rr][tid];
                g_num[((size_t)b*T_ + t)*D_ + tid] = sum;
            }
            __syncthreads();
        }
    }
}

// ---------------- k5: out = relu(relu((num/den)@W1+b1)@W2+b2) + R ----------------
__global__ void k5_ffn(const float* __restrict__ W1, const float* __restrict__ b1_,
                       const float* __restrict__ W2, const float* __restrict__ b2_,
                       const float* __restrict__ Zout, float* __restrict__ outO) {
    __shared__ __align__(16) float aBuf[32*D_];
    __shared__ __align__(16) float wBuf[32*D_];
    const int tid  = threadIdx.x;  // 256
    const int w    = tid >> 5, lane = tid & 31;
    const int row0 = blockIdx.x * 32;

    // denominator + a = num/den
#pragma unroll
    for (int rr = 0; rr < 4; rr++) {
        const int r = w*4 + rr;
        const size_t row = (size_t)row0 + r;
        float d = 0.f;
#pragma unroll
        for (int k = 0; k < 4; k++) {
            const int f = lane + 32*k;
            d += g_Q[row*D_ + f] * Zout[row*D_ + f];
        }
#pragma unroll
        for (int off = 16; off; off >>= 1) d += __shfl_xor_sync(0xffffffffu, d, off);
        const float rden = 1.0f / (d + 1e-5f);
#pragma unroll
        for (int k = 0; k < 4; k++) {
            const int f = lane + 32*k;
            aBuf[r*D_ + f] = g_num[row*D_ + f] * rden;
        }
    }
    const int rowg = w, colg = lane;
    float acc[4][4];

    // GEMM1: h = relu(a @ W1 + b1)
#pragma unroll
    for (int u = 0; u < 4; u++)
#pragma unroll
        for (int v = 0; v < 4; v++) acc[u][v] = 0.f;
    for (int kc = 0; kc < D_; kc += 32) {
        __syncthreads();
        for (int q = tid; q < 32*D_/4; q += 256)
            ((float4*)wBuf)[q] = ((const float4*)(W1 + (size_t)kc*D_))[q];
        __syncthreads();
#pragma unroll
        for (int k = 0; k < 32; k++) {
            const float4 wv = ((const float4*)(wBuf + k*D_))[colg];
#pragma unroll
            for (int u = 0; u < 4; u++) {
                const float a = aBuf[(rowg*4+u)*D_ + kc + k];
                acc[u][0] += a*wv.x; acc[u][1] += a*wv.y;
                acc[u][2] += a*wv.z; acc[u][3] += a*wv.w;
            }
        }
    }
    __syncthreads();
    {
        const float4 b1v = ((const float4*)b1_)[colg];
#pragma unroll
        for (int u = 0; u < 4; u++) {
            float4 h;
            h.x = fmaxf(acc[u][0] + b1v.x, 0.f);
            h.y = fmaxf(acc[u][1] + b1v.y, 0.f);
            h.z = fmaxf(acc[u][2] + b1v.z, 0.f);
            h.w = fmaxf(acc[u][3] + b1v.w, 0.f);
            *(float4*)&aBuf[(rowg*4+u)*D_ + colg*4] = h;
        }
    }
    // GEMM2: o = relu(h @ W2 + b2) + R
#pragma unroll
    for (int u = 0; u < 4; u++)
#pragma unroll
        for (int v = 0; v < 4; v++) acc[u][v] = 0.f;
    for (int kc = 0; kc < D_; kc += 32) {
        __syncthreads();
        for (int q = tid; q < 32*D_/4; q += 256)
            ((float4*)wBuf)[q] = ((const float4*)(W2 + (size_t)kc*D_))[q];
        __syncthreads();
#pragma unroll
        for (int k = 0; k < 32; k++) {
            const float4 wv = ((const float4*)(wBuf + k*D_))[colg];
#pragma unroll
            for (int u = 0; u < 4; u++) {
                const float a = aBuf[(rowg*4+u)*D_ + kc + k];
                acc[u][0] += a*wv.x; acc[u][1] += a*wv.y;
                acc[u][2] += a*wv.z; acc[u][3] += a*wv.w;
            }
        }
    }
    {
        const float4 b2v = ((const float4*)b2_)[colg];
#pragma unroll
        for (int u = 0; u < 4; u++) {
            const size_t row = (size_t)row0 + rowg*4 + u;
            const float4 rv = *(const float4*)(g_R + row*D_ + colg*4);
            float4 o;
            o.x = fmaxf(acc[u][0] + b2v.x, 0.f) + rv.x;
            o.y = fmaxf(acc[u][1] + b2v.y, 0.f) + rv.y;
            o.z = fmaxf(acc[u][2] + b2v.z, 0.f) + rv.z;
            o.w = fmaxf(acc[u][3] + b2v.w, 0.f) + rv.w;
            *(float4*)(outO + row*D_ + colg*4) = o;
        }
    }
}

// ---------------- launch ----------------
extern "C" void kernel_launch(void* const* d_in, const int* in_sizes, int n_in,
                              void* d_out, int out_size) {
    const float* x     = (const float*)d_in[0];
    const float* S0    = (const float*)d_in[1];
    const float* Z0    = (const float*)d_in[2];
    const float* gamma = (const float*)d_in[3];
    const float* beta  = (const float*)d_in[4];
    const float* Wk    = (const float*)d_in[5];
    const float* Wq    = (const float*)d_in[6];
    const float* Wv    = (const float*)d_in[7];
    const float* W1    = (const float*)d_in[8];
    const float* b1    = (const float*)d_in[9];
    const float* W2    = (const float*)d_in[10];
    const float* b2    = (const float*)d_in[11];
    const float* Ws    = (const float*)d_in[12];
    const float* bs    = (const float*)d_in[13];

    float* outO = (float*)d_out;                       // [B,T,D]
    float* outS = outO + (size_t)B_*T_*D_;             // [B,T,D*D]
    float* outZ = outS + (size_t)B_*T_*D_*D_;          // [B,T,D]

    const int smem_k1 = (32*FIN_ + 32*D_) * sizeof(float);   // 49152 bytes
    k1_ln_proj<<<(B_*T_)/32, 256, smem_k1>>>(x, gamma, beta, Wk, Wq, Wv, Ws, bs);
    k2_chunksum<<<dim3(C_, B_), 256>>>();
    k3_scan<<<(B_*D_*D_ + 255)/256, 256>>>();
    kZ_kernel<<<B_, D_>>>(Z0, outZ);
    k4_main<<<dim3(C_, B_), 1024>>>(S0, outS);
    k5_ffn<<<(B_*T_)/32, 256>>>(W1, b1, W2, b2, outZ, outO);
}

// round 2
// speedup vs baseline: 1.6113x; 1.6113x over previous
#include <cuda_runtime.h>
#include <math.h>

#define B_   8
#define T_   512
#define FIN_ 256
#define D_   128
#define C_   16          // chunks per batch
#define L_   32          // chunk length (T_/C_)
#define SUB_ 16          // sub-tile of timesteps kept in smem

// ---------------- scratch (device globals; no runtime allocation) ----------------
__device__ __align__(16) float g_XN[B_*T_*FIN_];   // normalized x
__device__ __align__(16) float g_K[B_*T_*D_];
__device__ __align__(16) float g_Q[B_*T_*D_];
__device__ __align__(16) float g_V[B_*T_*D_];
__device__ __align__(16) float g_R[B_*T_*D_];      // xn @ Ws + bs
__device__ __align__(16) float g_num[B_*T_*D_];    // numerator
__device__ __align__(16) float g_Soff[B_*C_*D_*D_];// chunk sums -> exclusive prefix
__device__ __align__(16) float g_Zsum[B_*C_*D_];   // chunk K sums -> exclusive prefix

// ---------------- k0: LayerNorm -> g_XN ----------------
// grid 128 x 256 threads; warp handles 4 rows
__global__ void k0_ln(const float* __restrict__ x,
                      const float* __restrict__ gamma, const float* __restrict__ beta) {
    const int tid  = threadIdx.x;
    const int w    = tid >> 5, lane = tid & 31;
    const int row0 = blockIdx.x * 32;

    float gv[8], bv[8];
#pragma unroll
    for (int k = 0; k < 8; k++) { gv[k] = gamma[lane + 32*k]; bv[k] = beta[lane + 32*k]; }

#pragma unroll
    for (int rr = 0; rr < 4; rr++) {
        const size_t r = (size_t)row0 + w*4 + rr;
        float s = 0.f, ss = 0.f, xv[8];
#pragma unroll
        for (int k = 0; k < 8; k++) {
            float v = x[r*FIN_ + lane + 32*k];
            xv[k] = v; s += v; ss += v*v;
        }
#pragma unroll
        for (int off = 16; off; off >>= 1) {
            s  += __shfl_xor_sync(0xffffffffu, s,  off);
            ss += __shfl_xor_sync(0xffffffffu, ss, off);
        }
        const float mu   = s * (1.0f/FIN_);
        const float rstd = rsqrtf(ss*(1.0f/FIN_) - mu*mu + 1e-5f);
#pragma unroll
        for (int k = 0; k < 8; k++)
            g_XN[r*FIN_ + lane + 32*k] = (xv[k]-mu)*rstd*gv[k] + bv[k];
    }
}

// ---------------- k1: projections (one matrix per blockIdx.y) ----------------
// grid (128, 4) x 128 threads, 32 rows/block, micro-tile 4x8
__global__ void k1_proj(const float* __restrict__ Wk, const float* __restrict__ Wq,
                        const float* __restrict__ Wv, const float* __restrict__ Ws,
                        const float* __restrict__ bs) {
    extern __shared__ float sm[];
    float* xb = sm;               // 32*256
    float* wb = sm + 32*FIN_;     // 32*128
    const int tid = threadIdx.x;       // 128
    const int tr  = tid >> 4;          // 0..7
    const int tc  = tid & 15;          // 0..15
    const int row0 = blockIdx.x * 32;
    const int m    = blockIdx.y;

    const float* Wp = (m==0) ? Wk : (m==1) ? Wq : (m==2) ? Wv : Ws;
    float*       Op = (m==0) ? g_K : (m==1) ? g_Q : (m==2) ? g_V : g_R;

    // load xn tile
    {
        const float4* xg = (const float4*)(g_XN + (size_t)row0 * FIN_);
        for (int q = tid; q < 32*FIN_/4; q += 128) ((float4*)xb)[q] = xg[q];
    }

    float acc[4][8];
#pragma unroll
    for (int u = 0; u < 4; u++)
#pragma unroll
        for (int v = 0; v < 8; v++) acc[u][v] = 0.f;

    for (int kc = 0; kc < FIN_; kc += 32) {
        __syncthreads();
        for (int q = tid; q < 32*D_/4; q += 128)
            ((float4*)wb)[q] = ((const float4*)(Wp + (size_t)kc*D_))[q];
        __syncthreads();
#pragma unroll
        for (int k = 0; k < 32; k++) {
            const float4 wA = ((const float4*)(wb + k*D_))[tc*2];
            const float4 wB = ((const float4*)(wb + k*D_))[tc*2+1];
#pragma unroll
            for (int u = 0; u < 4; u++) {
                const float a = xb[(tr*4+u)*FIN_ + kc + k];
                acc[u][0] += a*wA.x; acc[u][1] += a*wA.y;
                acc[u][2] += a*wA.z; acc[u][3] += a*wA.w;
                acc[u][4] += a*wB.x; acc[u][5] += a*wB.y;
                acc[u][6] += a*wB.z; acc[u][7] += a*wB.w;
            }
        }
    }

    float badd[8] = {0,0,0,0,0,0,0,0};
    if (m == 3) {
        float4 t0 = ((const float4*)bs)[tc*2];
        float4 t1 = ((const float4*)bs)[tc*2+1];
        badd[0]=t0.x; badd[1]=t0.y; badd[2]=t0.z; badd[3]=t0.w;
        badd[4]=t1.x; badd[5]=t1.y; badd[6]=t1.z; badd[7]=t1.w;
    }
#pragma unroll
    for (int u = 0; u < 4; u++) {
        float o[8];
#pragma unroll
        for (int v = 0; v < 8; v++) {
            float val = acc[u][v];
            if (m <= 1) val = (val > 0.f) ? (val + 1.f) : expf(val);   // elu + 1
            o[v] = val + badd[v];
        }
        float* dst = Op + ((size_t)(row0 + tr*4 + u))*D_ + tc*8;
        *(float4*)(dst)   = make_float4(o[0], o[1], o[2], o[3]);
        *(float4*)(dst+4) = make_float4(o[4], o[5], o[6], o[7]);
    }
}

// ---------------- k2: per-chunk outer-product sums + per-chunk K sums ----------------
__global__ void k2_chunksum() {
    const int c = blockIdx.x, b = blockIdx.y;
    const int tid = threadIdx.x;   // 256
    __shared__ __align__(16) float Ks[L_][D_];
    __shared__ __align__(16) float Vs[L_][D_];
    {
        const float4* kg = (const float4*)(g_K + ((size_t)b*T_ + c*L_)*D_);
        const float4* vg = (const float4*)(g_V + ((size_t)b*T_ + c*L_)*D_);
        for (int q = tid; q < L_*D_/4; q += 256) { ((float4*)Ks)[q] = kg[q]; ((float4*)Vs)[q] = vg[q]; }
    }
    __syncthreads();

    // chunk K sums for Z
    if (tid < D_) {
        float zs = 0.f;
#pragma unroll
        for (int t = 0; t < L_; t++) zs += Ks[t][tid];
        g_Zsum[((size_t)(b*C_ + c))*D_ + tid] = zs;
    }

    const int tr = tid >> 4, tc = tid & 15;  // 16x16, micro 8x8
    const int i0 = tr*8, j0 = tc*8;
    float acc[8][8];
#pragma unroll
    for (int u = 0; u < 8; u++)
#pragma unroll
        for (int v = 0; v < 8; v++) acc[u][v] = 0.f;

    for (int t = 0; t < L_; t++) {
        float k8[8], v8[8];
        *(float4*)(k8)   = *(const float4*)&Ks[t][i0];
        *(float4*)(k8+4) = *(const float4*)&Ks[t][i0+4];
        *(float4*)(v8)   = *(const float4*)&Vs[t][j0];
        *(float4*)(v8+4) = *(const float4*)&Vs[t][j0+4];
#pragma unroll
        for (int u = 0; u < 8; u++)
#pragma unroll
            for (int v = 0; v < 8; v++) acc[u][v] += k8[u]*v8[v];
    }
    float* op = g_Soff + (((size_t)(b*C_ + c))*D_ + i0)*D_ + j0;
#pragma unroll
    for (int u = 0; u < 8; u++) {
        *(float4*)(op + (size_t)u*D_)     = make_float4(acc[u][0],acc[u][1],acc[u][2],acc[u][3]);
        *(float4*)(op + (size_t)u*D_ + 4) = make_float4(acc[u][4],acc[u][5],acc[u][6],acc[u][7]);
    }
}

// ---------------- k3: in-place exclusive scan of chunk sums (S and Z) over c ----------------
__global__ void k3_scan() {
    const int gid = blockIdx.x * blockDim.x + threadIdx.x;
    if (gid < B_*D_*D_) {
        const int b  = gid >> 14;            // D_*D_ = 16384
        const int ij = gid & (D_*D_ - 1);
        const size_t base = (size_t)b*C_*D_*D_ + ij;
        float run = 0.f;
#pragma unroll
        for (int c = 0; c < C_; c++) {
            const float tmp = g_Soff[base + (size_t)c*D_*D_];
            g_Soff[base + (size_t)c*D_*D_] = run;
            run += tmp;
        }
    } else {
        const int zid = gid - B_*D_*D_;
        if (zid < B_*D_) {
            const int b = zid >> 7, i = zid & (D_-1);
            const size_t base = (size_t)b*C_*D_ + i;
            float run = 0.f;
#pragma unroll
            for (int c = 0; c < C_; c++) {
                const float tmp = g_Zsum[base + (size_t)c*D_];
                g_Zsum[base + (size_t)c*D_] = run;
                run += tmp;
            }
        }
    }
}

// ---------------- k4: main scan — S state in registers, write S + Z, compute numerator ----------------
__global__ void __launch_bounds__(1024, 1)
k4_main(const float* __restrict__ S0, const float* __restrict__ Z0,
        float* __restrict__ outS, float* __restrict__ outZ) {
    const int c = blockIdx.x, b = blockIdx.y;
    const int tid = threadIdx.x;         // 1024
    const int ri = tid >> 5;             // 0..31
    const int jg = tid & 31;             // 0..31
    const int i0 = ri << 2, j0 = jg << 2;

    extern __shared__ float dsm[];
    float* Ks   = dsm;                         // [SUB_][D_]
    float* Vs   = Ks + SUB_*D_;                // [SUB_][D_]
    float* Qs   = Vs + SUB_*D_;                // [SUB_][D_]
    float* part = Qs + SUB_*D_;                // [2][32][D_]

    float s[4][4];
    {
        const float* soff = g_Soff + (((size_t)(b*C_ + c))*D_ + i0)*D_ + j0;
        const float* s0g  = S0 + ((size_t)b*D_ + i0)*D_ + j0;
#pragma unroll
        for (int u = 0; u < 4; u++) {
            const float4 a = *(const float4*)(soff + (size_t)u*D_);
            const float4 z = *(const float4*)(s0g  + (size_t)u*D_);
            s[u][0] = a.x + z.x; s[u][1] = a.y + z.y;
            s[u][2] = a.z + z.z; s[u][3] = a.w + z.w;
        }
    }

    float zrun = 0.f;
    if (tid < D_) zrun = Z0[b*D_ + tid] + g_Zsum[((size_t)(b*C_ + c))*D_ + tid];

    const int t0 = c * L_;
    for (int sub = 0; sub < L_/SUB_; sub++) {
        const int tg = t0 + sub*SUB_;
        {
            const float4* kg = (const float4*)(g_K + ((size_t)b*T_ + tg)*D_);
            const float4* vg = (const float4*)(g_V + ((size_t)b*T_ + tg)*D_);
            const float4* qg = (const float4*)(g_Q + ((size_t)b*T_ + tg)*D_);
            const int h = tid & 511;     // SUB_*D_/4 = 512
            if (tid < 512) { ((float4*)Ks)[h] = kg[h]; ((float4*)Vs)[h] = vg[h]; }
            else           { ((float4*)Qs)[h] = qg[h]; }
        }
        __syncthreads();

        for (int tt = 0; tt < SUB_; tt++) {
            const int t = tg + tt;
            const float4 kv = *(const float4*)&Ks[tt*D_ + i0];
            const float4 vv = *(const float4*)&Vs[tt*D_ + j0];
            const float4 qv = *(const float4*)&Qs[tt*D_ + i0];
            const float kk[4] = {kv.x, kv.y, kv.z, kv.w};
            const float vb[4] = {vv.x, vv.y, vv.z, vv.w};
            const float qq[4] = {qv.x, qv.y, qv.z, qv.w};
            float p0 = 0.f, p1 = 0.f, p2 = 0.f, p3 = 0.f;
            float* orow = outS + (((size_t)b*T_ + t)*D_ + i0)*D_ + j0;
#pragma unroll
            for (int u = 0; u < 4; u++) {
                s[u][0] += kk[u]*vb[0];
                s[u][1] += kk[u]*vb[1];
                s[u][2] += kk[u]*vb[2];
                s[u][3] += kk[u]*vb[3];
                __stcs((float4*)(orow + (size_t)u*D_),
                       make_float4(s[u][0], s[u][1], s[u][2], s[u][3]));
                p0 += qq[u]*s[u][0];
                p1 += qq[u]*s[u][1];
                p2 += qq[u]*s[u][2];
                p3 += qq[u]*s[u][3];
            }
            float* pb = part + (tt & 1)*32*D_;
            *(float4*)&pb[ri*D_ + j0] = make_float4(p0, p1, p2, p3);
            if (tid < D_) {
                zrun += Ks[tt*D_ + tid];
                outZ[((size_t)b*T_ + t)*D_ + tid] = zrun;
            }
            __syncthreads();
            if (tid < D_) {
                float sum = 0.f;
#pragma unroll
                for (int rr = 0; rr < 32; rr++) sum += pb[rr*D_ + tid];
                g_num[((size_t)b*T_ + t)*D_ + tid] = sum;
            }
        }
        __syncthreads();   // protect smem tiles before next sub reload
    }
}

// ---------------- k5: out = relu(relu((num/den)@W1+b1)@W2+b2) + R ----------------
__global__ void k5_ffn(const float* __restrict__ W1, const float* __restrict__ b1_,
                       const float* __restrict__ W2, const float* __restrict__ b2_,
                       const float* __restrict__ Zout, float* __restrict__ outO) {
    __shared__ __align__(16) float aBuf[32*D_];
    __shared__ __align__(16) float wBuf[32*D_];
    const int tid  = threadIdx.x;  // 256
    const int w    = tid >> 5, lane = tid & 31;
    const int row0 = blockIdx.x * 32;

#pragma unroll
    for (int rr = 0; rr < 4; rr++) {
        const int r = w*4 + rr;
        const size_t row = (size_t)row0 + r;
        float d = 0.f;
#pragma unroll
        for (int k = 0; k < 4; k++) {
            const int f = lane + 32*k;
            d += g_Q[row*D_ + f] * Zout[row*D_ + f];
        }
#pragma unroll
        for (int off = 16; off; off >>= 1) d += __shfl_xor_sync(0xffffffffu, d, off);
        const float rden = 1.0f / (d + 1e-5f);
#pragma unroll
        for (int k = 0; k < 4; k++) {
            const int f = lane + 32*k;
            aBuf[r*D_ + f] = g_num[row*D_ + f] * rden;
        }
    }
    const int rowg = w, colg = lane;
    float acc[4][4];

#pragma unroll
    for (int u = 0; u < 4; u++)
#pragma unroll
        for (int v = 0; v < 4; v++) acc[u][v] = 0.f;
    for (int kc = 0; kc < D_; kc += 32) {
        __syncthreads();
        for (int q = tid; q < 32*D_/4; q += 256)
            ((float4*)wBuf)[q] = ((const float4*)(W1 + (size_t)kc*D_))[q];
        __syncthreads();
#pragma unroll
        for (int k = 0; k < 32; k++) {
            const float4 wv = ((const float4*)(wBuf + k*D_))[colg];
#pragma unroll
            for (int u = 0; u < 4; u++) {
                const float a = aBuf[(rowg*4+u)*D_ + kc + k];
                acc[u][0] += a*wv.x; acc[u][1] += a*wv.y;
                acc[u][2] += a*wv.z; acc[u][3] += a*wv.w;
            }
        }
    }
    __syncthreads();
    {
        const float4 b1v = ((const float4*)b1_)[colg];
#pragma unroll
        for (int u = 0; u < 4; u++) {
            float4 h;
            h.x = fmaxf(acc[u][0] + b1v.x, 0.f);
            h.y = fmaxf(acc[u][1] + b1v.y, 0.f);
            h.z = fmaxf(acc[u][2] + b1v.z, 0.f);
            h.w = fmaxf(acc[u][3] + b1v.w, 0.f);
            *(float4*)&aBuf[(rowg*4+u)*D_ + colg*4] = h;
        }
    }
#pragma unroll
    for (int u = 0; u < 4; u++)
#pragma unroll
        for (int v = 0; v < 4; v++) acc[u][v] = 0.f;
    for (int kc = 0; kc < D_; kc += 32) {
        __syncthreads();
        for (int q = tid; q < 32*D_/4; q += 256)
            ((float4*)wBuf)[q] = ((const float4*)(W2 + (size_t)kc*D_))[q];
        __syncthreads();
#pragma unroll
        for (int k = 0; k < 32; k++) {
            const float4 wv = ((const float4*)(wBuf + k*D_))[colg];
#pragma unroll
            for (int u = 0; u < 4; u++) {
                const float a = aBuf[(rowg*4+u)*D_ + kc + k];
                acc[u][0] += a*wv.x; acc[u][1] += a*wv.y;
                acc[u][2] += a*wv.z; acc[u][3] += a*wv.w;
            }
        }
    }
    {
        const float4 b2v = ((const float4*)b2_)[colg];
#pragma unroll
        for (int u = 0; u < 4; u++) {
            const size_t row = (size_t)row0 + rowg*4 + u;
            const float4 rv = *(const float4*)(g_R + row*D_ + colg*4);
            float4 o;
            o.x = fmaxf(acc[u][0] + b2v.x, 0.f) + rv.x;
            o.y = fmaxf(acc[u][1] + b2v.y, 0.f) + rv.y;
            o.z = fmaxf(acc[u][2] + b2v.z, 0.f) + rv.z;
            o.w = fmaxf(acc[u][3] + b2v.w, 0.f) + rv.w;
            *(float4*)(outO + row*D_ + colg*4) = o;
        }
    }
}

// ---------------- launch ----------------
extern "C" void kernel_launch(void* const* d_in, const int* in_sizes, int n_in,
                              void* d_out, int out_size) {
    const float* x     = (const float*)d_in[0];
    const float* S0    = (const float*)d_in[1];
    const float* Z0    = (const float*)d_in[2];
    const float* gamma = (const float*)d_in[3];
    const float* beta  = (const float*)d_in[4];
    const float* Wk    = (const float*)d_in[5];
    const float* Wq    = (const float*)d_in[6];
    const float* Wv    = (const float*)d_in[7];
    const float* W1    = (const float*)d_in[8];
    const float* b1    = (const float*)d_in[9];
    const float* W2    = (const float*)d_in[10];
    const float* b2    = (const float*)d_in[11];
    const float* Ws    = (const float*)d_in[12];
    const float* bs    = (const float*)d_in[13];

    float* outO = (float*)d_out;                       // [B,T,D]
    float* outS = outO + (size_t)B_*T_*D_;             // [B,T,D*D]
    float* outZ = outS + (size_t)B_*T_*D_*D_;          // [B,T,D]

    static bool attr_done = false;
    const int smem_k4 = (3*SUB_*D_ + 2*32*D_) * sizeof(float);   // 57344
    if (!attr_done) {
        cudaFuncSetAttribute(k4_main, cudaFuncAttributeMaxDynamicSharedMemorySize, smem_k4);
        attr_done = true;
    }

    const int smem_k1 = (32*FIN_ + 32*D_) * sizeof(float);   // 49152 bytes

    k0_ln<<<(B_*T_)/32, 256>>>(x, gamma, beta);
    k1_proj<<<dim3((B_*T_)/32, 4), 128, smem_k1>>>(Wk, Wq, Wv, Ws, bs);
    k2_chunksum<<<dim3(C_, B_), 256>>>();
    k3_scan<<<(B_*D_*D_ + B_*D_ + 255)/256, 256>>>();
    k4_main<<<dim3(C_, B_), 1024, smem_k4>>>(S0, Z0, outS, outZ);
    k5_ffn<<<(B_*T_)/32, 256>>>(W1, b1, W2, b2, outZ, outO);
}